// round 12
// baseline (speedup 1.0000x reference)
#include <cuda_runtime.h>
#include <cuda_bf16.h>
#include <cstdint>
#include <cstddef>

// Problem constants
#define N_    32
#define C_    64
#define T_    1024
#define V_    25
#define K_    3
#define O_    192
#define EPSV  1e-5f

#define TPOS  4
#define NBLK1 (N_ * (T_ / TPOS))   // 8192
#define THREADS 512

// ---- smem layout (bytes) ----
#define WHI_B   0        // bf16 [192][64], SW128-swizzled 128B rows
#define WLO_B   24576
#define XHI_B   49152    // bf16 [104 pos][64 cin], SW128 rows (rows 100-103 unused)
#define XLO_B   62464
#define Y_B     75776    // f32 [192][105]  = 80640 B  (stride 105: col reads conflict-free)
#define AF_B    156416   // f32 [3][25][28] = 8400 B
#define BE_B    164816   // f32 [64][25]    = 6400 B
#define CS_B    171216   // f32 [3][25] (+pad)
#define SMEM_TOTAL 171520
// overlay (valid after conv; overlaps W/X tiles which are dead post-MMA):
#define AGS_B   0        // f32 [64][101] = 25856 B
#define PART_B  26624    // f32 [1024]    = 4096 B

// ---- device scratch ----
__device__ float g_agg[(size_t)N_ * C_ * T_ * V_];
__device__ float g_psum[NBLK1 * C_];
__device__ float g_psumsq[NBLK1 * C_];
__device__ float g_scale[C_];
__device__ float g_shift[C_];

#define SWZ128(o) ((o) ^ (((o) >> 3) & 0x70))

__device__ __forceinline__ uint32_t smem_u32(const void* p) {
    uint32_t a;
    asm("{ .reg .u64 t; cvta.to.shared.u64 t, %1; cvt.u32.u64 %0, t; }" : "=r"(a) : "l"(p));
    return a;
}

// ---- packed fp32x2 ----
__device__ __forceinline__ unsigned long long pack2(float a, float b) {
    unsigned long long r;
    asm("mov.b64 %0, {%1, %2};" : "=l"(r) : "f"(a), "f"(b));
    return r;
}
__device__ __forceinline__ void unpack2(unsigned long long p, float& a, float& b) {
    asm("mov.b64 {%0, %1}, %2;" : "=f"(a), "=f"(b) : "l"(p));
}
__device__ __forceinline__ unsigned long long fma2(unsigned long long a,
                                                   unsigned long long b,
                                                   unsigned long long c) {
    unsigned long long d;
    asm("fma.rn.f32x2 %0, %1, %2, %3;" : "=l"(d) : "l"(a), "l"(b), "l"(c));
    return d;
}

// ---- mma.sync / ldmatrix (plain sm_80+ PTX; works on compute_103) ----
__device__ __forceinline__ void ldsm_x4(uint32_t addr, uint32_t* r) {
    asm volatile("ldmatrix.sync.aligned.m8n8.x4.shared.b16 {%0,%1,%2,%3}, [%4];"
        : "=r"(r[0]), "=r"(r[1]), "=r"(r[2]), "=r"(r[3]) : "r"(addr));
}
__device__ __forceinline__ void ldsm_x2(uint32_t addr, uint32_t& r0, uint32_t& r1) {
    asm volatile("ldmatrix.sync.aligned.m8n8.x2.shared.b16 {%0,%1}, [%2];"
        : "=r"(r0), "=r"(r1) : "r"(addr));
}
__device__ __forceinline__ void mma_bf16(float& d0, float& d1, float& d2, float& d3,
                                         const uint32_t* a, uint32_t b0, uint32_t b1) {
    asm volatile("mma.sync.aligned.m16n8k16.row.col.f32.bf16.bf16.f32 "
        "{%0,%1,%2,%3}, {%4,%5,%6,%7}, {%8,%9}, {%0,%1,%2,%3};"
        : "+f"(d0), "+f"(d1), "+f"(d2), "+f"(d3)
        : "r"(a[0]), "r"(a[1]), "r"(a[2]), "r"(a[3]), "r"(b0), "r"(b1));
}

// ============================================================================
// Pass 1: bf16 hi/lo-split HMMA conv + scalar f32x2 aggregation + BN partials
// ============================================================================
__global__ __launch_bounds__(THREADS, 1)
void k_gcn(const float* __restrict__ x, const float* __restrict__ W,
           const float* __restrict__ b, const float* __restrict__ A,
           const float* __restrict__ PA)
{
    extern __shared__ char smem[];
    const uint32_t sbase = smem_u32(smem);
    float* Ysm = (float*)(smem + Y_B);
    float* Af  = (float*)(smem + AF_B);
    float* be  = (float*)(smem + BE_B);
    float* cs  = (float*)(smem + CS_B);

    const int tid = threadIdx.x;
    const int wid = tid >> 5;
    const int lid = tid & 31;

    const int bi = blockIdx.x;
    const int n  = bi >> 8;
    const int t0 = (bi & 255) * TPOS;

    // ---- setup: convert W and x to bf16 hi/lo, build Af ----
    for (int i = tid; i < O_ * C_; i += THREADS) {       // W[o][cin]
        int o = i >> 6, cin = i & 63;
        float wv = W[i];
        __nv_bfloat16 h = __float2bfloat16(wv);
        __nv_bfloat16 l = __float2bfloat16(wv - __bfloat162float(h));
        uint32_t off = SWZ128((uint32_t)(o * 128 + cin * 2));
        *(__nv_bfloat16*)(smem + WHI_B + off) = h;
        *(__nv_bfloat16*)(smem + WLO_B + off) = l;
    }
    const float* xb = x + (size_t)n * (C_ * T_ * V_) + (size_t)t0 * V_;
    for (int i = tid; i < 6400; i += THREADS) {          // -> X[pos][cin]
        int cin = i / 100, r = i % 100;
        float xv = xb[(size_t)cin * (T_ * V_) + r];
        __nv_bfloat16 h = __float2bfloat16(xv);
        __nv_bfloat16 l = __float2bfloat16(xv - __bfloat162float(h));
        uint32_t off = SWZ128((uint32_t)(r * 128 + cin * 2));
        *(__nv_bfloat16*)(smem + XHI_B + off) = h;
        *(__nv_bfloat16*)(smem + XLO_B + off) = l;
    }
    // zero unused X rows 100-103 (read by nt=12 ldmatrix; values discarded but
    // keep them defined)
    for (int i = tid; i < 4 * 64; i += THREADS) {
        int r = 100 + (i >> 6), cin = i & 63;
        uint32_t off = SWZ128((uint32_t)(r * 128 + cin * 2));
        *(__nv_bfloat16*)(smem + XHI_B + off) = __float2bfloat16(0.f);
        *(__nv_bfloat16*)(smem + XLO_B + off) = __float2bfloat16(0.f);
    }
    for (int i = tid; i < K_ * V_ * V_; i += THREADS) {
        int kv = i / 25, w = i % 25;
        Af[kv * 28 + w] = A[i] + PA[i];
    }
    for (int i = tid; i < 75 * 3; i += THREADS) {        // zero w-pads
        int kv = i / 3, j = i % 3;
        Af[kv * 28 + 25 + j] = 0.f;
    }
    __syncthreads();

    if (tid < 75) {                                       // colsum
        int k = tid / 25, w = tid % 25;
        float s = 0.f;
        #pragma unroll
        for (int v = 0; v < 25; v++) s += Af[(k * 25 + v) * 28 + w];
        cs[tid] = s;
    }
    __syncthreads();
    for (int i = tid; i < C_ * V_; i += THREADS) {        // effective bias
        int c = i / 25, w = i % 25;
        float s = 0.f;
        #pragma unroll
        for (int k = 0; k < 3; k++) s += __ldg(&b[k * 64 + c]) * cs[k * 25 + w];
        be[i] = s;
    }
    __syncthreads();

    // ---- conv via mma.sync: warps 0-11, warp = one m16 row block of W ----
    if (wid < 12) {
        const int mt = wid;
        // A fragments (hi+lo, 4 k-steps), hoisted: 32 regs
        uint32_t ahi[4][4], alo[4][4];
        {
            const int q = lid >> 3, ri = lid & 7;
            const int arow = mt * 16 + ((q & 1) << 3) + ri;
            const int acol0 = (q >> 1) << 4;
            #pragma unroll
            for (int ks = 0; ks < 4; ks++) {
                uint32_t off = SWZ128((uint32_t)(arow * 128 + ks * 32 + acol0));
                ldsm_x4(sbase + WHI_B + off, ahi[ks]);
                ldsm_x4(sbase + WLO_B + off, alo[ks]);
            }
        }
        const int l4 = lid & 15;
        const int brow_in = l4 & 7;
        const int bcol0 = ((l4 >> 3) & 1) << 4;

        for (int nt = 0; nt < 13; nt++) {
            float d0 = 0.f, d1 = 0.f, d2 = 0.f, d3 = 0.f;
            const int brow = nt * 8 + brow_in;
            #pragma unroll
            for (int ks = 0; ks < 4; ks++) {
                uint32_t off = SWZ128((uint32_t)(brow * 128 + ks * 32 + bcol0));
                uint32_t bh0, bh1, bl0, bl1;
                ldsm_x2(sbase + XHI_B + off, bh0, bh1);
                ldsm_x2(sbase + XLO_B + off, bl0, bl1);
                mma_bf16(d0, d1, d2, d3, ahi[ks], bh0, bh1);   // hi*hi
                mma_bf16(d0, d1, d2, d3, alo[ks], bh0, bh1);   // lo*hi
                mma_bf16(d0, d1, d2, d3, ahi[ks], bl0, bl1);   // hi*lo
            }
            // scalar stores: stride 105 is odd, so float2 would be misaligned
            const int r0 = mt * 16 + (lid >> 2);
            const int c0 = nt * 8 + (lid & 3) * 2;
            Ysm[r0 * 105 + c0]             = d0;
            Ysm[r0 * 105 + c0 + 1]         = d1;
            Ysm[(r0 + 8) * 105 + c0]       = d2;
            Ysm[(r0 + 8) * 105 + c0 + 1]   = d3;
        }
    }
    __syncthreads();     // Y ready; W/X smem dead -> overlay ags/part

    float* ags  = (float*)(smem + AGS_B);
    float* part = (float*)(smem + PART_B);

    // ---- aggregation: thread owns (c, p, w-half) ----
    {
        const int c = tid & 63;
        const int p = (tid >> 6) & 3;
        const int h = tid >> 8;          // 0: w 0-11 ; 1: w 12-23 (+24)
        const int w0 = h * 12;

        unsigned long long acc[6];
        float acc24 = 0.f;
        {
            const float* bec = be + c * 25 + w0;
            #pragma unroll
            for (int j = 0; j < 6; j++) acc[j] = pack2(bec[2 * j], bec[2 * j + 1]);
            if (h) acc24 = be[c * 25 + 24];
        }

        #pragma unroll 1
        for (int k = 0; k < 3; k++) {
            const float* yrow = Ysm + (k * 64 + c) * 105 + p * 25;
            const float* afk  = Af + k * 25 * 28 + w0;
            #pragma unroll 5
            for (int v = 0; v < 25; v++) {
                float yv = yrow[v];
                unsigned long long yp = pack2(yv, yv);
                // afk row base bytes are 16B-aligned for both h values
                const ulonglong2* a2 = (const ulonglong2*)(afk + v * 28);
                ulonglong2 aa0 = a2[0];
                acc[0] = fma2(yp, aa0.x, acc[0]);
                acc[1] = fma2(yp, aa0.y, acc[1]);
                unsigned long long aa2 = *(const unsigned long long*)(afk + v * 28 + 4);
                unsigned long long aa3 = *(const unsigned long long*)(afk + v * 28 + 6);
                acc[2] = fma2(yp, aa2, acc[2]);
                acc[3] = fma2(yp, aa3, acc[3]);
                unsigned long long aa4 = *(const unsigned long long*)(afk + v * 28 + 8);
                unsigned long long aa5 = *(const unsigned long long*)(afk + v * 28 + 10);
                acc[4] = fma2(yp, aa4, acc[4]);
                acc[5] = fma2(yp, aa5, acc[5]);
                if (h) acc24 = fmaf(yv, Af[(k * 25 + v) * 28 + 24], acc24);
            }
        }

        // unpack, stats, stage
        float vals[13];
        #pragma unroll
        for (int j = 0; j < 6; j++) unpack2(acc[j], vals[2 * j], vals[2 * j + 1]);
        vals[12] = acc24;
        const int nv = h ? 13 : 12;

        float s1 = 0.f, s2 = 0.f;
        #pragma unroll
        for (int j = 0; j < 13; j++)
            if (j < nv) { float a = vals[j]; s1 += a; s2 += a * a; }

        float* ar = ags + c * 101 + p * 25 + w0;
        #pragma unroll
        for (int j = 0; j < 13; j++)
            if (j < nv) ar[j] = vals[j];

        part[tid] = s1;
        part[THREADS + tid] = s2;
    }
    __syncthreads();

    // ---- coalesced store + deterministic partial reduce ----
    float* ob = g_agg + ((size_t)(n * 64) * T_ + t0) * V_;
    for (int i = tid; i < 6400; i += THREADS) {
        int cc = i / 100, r = i % 100;
        ob[(size_t)cc * (T_ * V_) + r] = ags[cc * 101 + r];
    }
    if (tid < 64) {
        float p1 = 0.f, p2 = 0.f;
        #pragma unroll
        for (int j = 0; j < 8; j++) {
            p1 += part[tid + 64 * j];
            p2 += part[THREADS + tid + 64 * j];
        }
        g_psum[bi * 64 + tid]   = p1;
        g_psumsq[bi * 64 + tid] = p2;
    }
}

// ============================================================================
// Pass 2: reduce partials -> per-channel scale/shift
// ============================================================================
__global__ void k_stats(const float* __restrict__ gamma, const float* __restrict__ beta)
{
    const int ch = blockIdx.x;
    const int tid = threadIdx.x;
    __shared__ float s1s[256], s2s[256];
    float s1 = 0.f, s2 = 0.f;
    for (int j = tid; j < NBLK1; j += 256) {
        s1 += g_psum[j * 64 + ch];
        s2 += g_psumsq[j * 64 + ch];
    }
    s1s[tid] = s1; s2s[tid] = s2;
    __syncthreads();
    for (int st = 128; st > 0; st >>= 1) {
        if (tid < st) { s1s[tid] += s1s[tid + st]; s2s[tid] += s2s[tid + st]; }
        __syncthreads();
    }
    if (tid == 0) {
        const float cnt = (float)N_ * T_ * V_;
        float mu   = s1s[0] / cnt;
        float var  = s2s[0] / cnt - mu * mu;
        float rstd = rsqrtf(var + EPSV);
        float sc   = gamma[ch] * rstd;
        g_scale[ch] = sc;
        g_shift[ch] = beta[ch] - mu * sc;
    }
}

// ============================================================================
// Pass 3: out = relu(agg*scale + shift + x), float4
// ============================================================================
__global__ __launch_bounds__(256)
void k_out(const float* __restrict__ x, float* __restrict__ out)
{
    const int total4 = (N_ * C_ * T_ * V_) / 4;
    int i = blockIdx.x * blockDim.x + threadIdx.x;
    if (i >= total4) return;
    const float4* x4 = (const float4*)x;
    const float4* a4 = (const float4*)g_agg;
    float4* o4 = (float4*)out;

    int c = (i / 6400) & 63;
    float sc = g_scale[c], sh = g_shift[c];
    float4 a = a4[i], xv = x4[i];
    float4 r;
    r.x = fmaxf(fmaf(a.x, sc, sh) + xv.x, 0.f);
    r.y = fmaxf(fmaf(a.y, sc, sh) + xv.y, 0.f);
    r.z = fmaxf(fmaf(a.z, sc, sh) + xv.z, 0.f);
    r.w = fmaxf(fmaf(a.w, sc, sh) + xv.w, 0.f);
    o4[i] = r;
}

// ============================================================================
extern "C" void kernel_launch(void* const* d_in, const int* in_sizes, int n_in,
                              void* d_out, int out_size)
{
    const float* x     = (const float*)d_in[0];
    const float* W     = (const float*)d_in[1];
    const float* b     = (const float*)d_in[2];
    const float* A     = (const float*)d_in[3];
    const float* PA    = (const float*)d_in[4];
    const float* gamma = (const float*)d_in[5];
    const float* beta  = (const float*)d_in[6];
    float* out = (float*)d_out;

    cudaFuncSetAttribute(k_gcn, cudaFuncAttributeMaxDynamicSharedMemorySize, SMEM_TOTAL);

    k_gcn<<<NBLK1, THREADS, SMEM_TOTAL>>>(x, W, b, A, PA);
    k_stats<<<C_, 256>>>(gamma, beta);
    const int total4 = (N_ * C_ * T_ * V_) / 4;
    k_out<<<(total4 + 255) / 256, 256>>>(x, out);
}

// round 13
// speedup vs baseline: 1.1220x; 1.1220x over previous
#include <cuda_runtime.h>
#include <cuda_bf16.h>
#include <cstdint>
#include <cstddef>

// Problem constants
#define N_    32
#define C_    64
#define T_    1024
#define V_    25
#define K_    3
#define O_    192
#define EPSV  1e-5f

#define TPOS  4
#define NBLK1 (N_ * (T_ / TPOS))   // 8192
#define THREADS 512

// ---- smem layout (bytes) for k_gcn ----
#define XHI_B   0        // bf16 [104 pos][64 cin] SW128 rows (13312 B)
#define XLO_B   13312
#define Y_B     26624    // f32 [192][105] = 80640 B (stride 105: conflict-free cols)
#define AF_B    107264   // f32 [3][25][28] = 8400 B
#define BE_B    115664   // f32 [64][25]   = 6400 B
#define PART_B  122064   // f32 [1024]     = 4096 B
#define SMEM_TOTAL 126208
// overlay after MMA (X dead): ags [64][101] f32 = 25856 B at offset 0
#define AGS_B   0

// ---- device scratch ----
__device__ float    g_agg[(size_t)N_ * C_ * T_ * V_];
__device__ float    g_psum[NBLK1 * C_];
__device__ float    g_psumsq[NBLK1 * C_];
__device__ float    g_scale[C_];
__device__ float    g_shift[C_];
__device__ uint32_t g_wfrag[48 * 2 * 32 * 4];   // [mt*4+ks][hi/lo][lane][4 regs]
__device__ float    g_af[K_ * V_ * 28];         // padded, pads zeroed
__device__ float    g_beff[C_ * V_];            // effective bias

#define SWZ128(o) ((o) ^ (((o) >> 3) & 0x70))

__device__ __forceinline__ uint32_t smem_u32(const void* p) {
    uint32_t a;
    asm("{ .reg .u64 t; cvta.to.shared.u64 t, %1; cvt.u32.u64 %0, t; }" : "=r"(a) : "l"(p));
    return a;
}

// ---- packed fp32x2 ----
__device__ __forceinline__ unsigned long long pack2(float a, float b) {
    unsigned long long r;
    asm("mov.b64 %0, {%1, %2};" : "=l"(r) : "f"(a), "f"(b));
    return r;
}
__device__ __forceinline__ void unpack2(unsigned long long p, float& a, float& b) {
    asm("mov.b64 {%0, %1}, %2;" : "=f"(a), "=f"(b) : "l"(p));
}
__device__ __forceinline__ unsigned long long fma2(unsigned long long a,
                                                   unsigned long long b,
                                                   unsigned long long c) {
    unsigned long long d;
    asm("fma.rn.f32x2 %0, %1, %2, %3;" : "=l"(d) : "l"(a), "l"(b), "l"(c));
    return d;
}

// ---- mma.sync / ldmatrix (plain sm_80+ PTX) ----
__device__ __forceinline__ void ldsm_x4(uint32_t addr, uint32_t* r) {
    asm volatile("ldmatrix.sync.aligned.m8n8.x4.shared.b16 {%0,%1,%2,%3}, [%4];"
        : "=r"(r[0]), "=r"(r[1]), "=r"(r[2]), "=r"(r[3]) : "r"(addr));
}
__device__ __forceinline__ void mma_bf16(float& d0, float& d1, float& d2, float& d3,
                                         uint4 a, uint32_t b0, uint32_t b1) {
    asm volatile("mma.sync.aligned.m16n8k16.row.col.f32.bf16.bf16.f32 "
        "{%0,%1,%2,%3}, {%4,%5,%6,%7}, {%8,%9}, {%0,%1,%2,%3};"
        : "+f"(d0), "+f"(d1), "+f"(d2), "+f"(d3)
        : "r"(a.x), "r"(a.y), "r"(a.z), "r"(a.w), "r"(b0), "r"(b1));
}

// ============================================================================
// k_prep: once per launch — W fragments (bf16 hi/lo, mma A-frag order),
//         Af = A+PA (padded), effective bias be.
// ============================================================================
__global__ __launch_bounds__(1024)
void k_prep(const float* __restrict__ W, const float* __restrict__ b,
            const float* __restrict__ A, const float* __restrict__ PA)
{
    __shared__ float saf[K_ * V_ * 28];
    __shared__ float scs[K_ * V_];
    const int tid = threadIdx.x;

    // W fragments: value (mtks, lane, j) -> rows/cols per PTX m16n8k16 A-frag
    for (int idx = tid; idx < 6144; idx += 1024) {
        int j    = idx & 3;
        int lane = (idx >> 2) & 31;
        int mtks = idx >> 7;
        int mt = mtks >> 2, ks = mtks & 3;
        int g = lane >> 2, tg = lane & 3;
        int row = mt * 16 + g + ((j & 1) << 3);
        int col = ks * 16 + tg * 2 + ((j >> 1) << 3);
        float w0 = W[row * 64 + col], w1 = W[row * 64 + col + 1];
        __nv_bfloat16 h0 = __float2bfloat16(w0);
        __nv_bfloat16 h1 = __float2bfloat16(w1);
        __nv_bfloat16 l0 = __float2bfloat16(w0 - __bfloat162float(h0));
        __nv_bfloat16 l1 = __float2bfloat16(w1 - __bfloat162float(h1));
        uint32_t hw = (uint32_t)__bfloat16_as_ushort(h0) | ((uint32_t)__bfloat16_as_ushort(h1) << 16);
        uint32_t lw = (uint32_t)__bfloat16_as_ushort(l0) | ((uint32_t)__bfloat16_as_ushort(l1) << 16);
        g_wfrag[((mtks * 2 + 0) * 32 + lane) * 4 + j] = hw;
        g_wfrag[((mtks * 2 + 1) * 32 + lane) * 4 + j] = lw;
    }
    // Af padded
    for (int i = tid; i < K_ * V_ * 28; i += 1024) {
        int kv = i / 28, w = i % 28;
        float v = (w < 25) ? (A[kv * 25 + w] + PA[kv * 25 + w]) : 0.f;
        saf[i] = v;
        g_af[i] = v;
    }
    __syncthreads();
    if (tid < 75) {
        int k = tid / 25, w = tid % 25;
        float s = 0.f;
        #pragma unroll
        for (int v = 0; v < 25; v++) s += saf[(k * 25 + v) * 28 + w];
        scs[tid] = s;
    }
    __syncthreads();
    for (int i = tid; i < C_ * V_; i += 1024) {
        int c = i / 25, w = i % 25;
        float s = 0.f;
        #pragma unroll
        for (int k = 0; k < 3; k++) s += b[k * 64 + c] * scs[k * 25 + w];
        g_beff[i] = s;
    }
}

// ============================================================================
// Pass 1: HMMA conv (A-frags from gmem, 16-warp items, 3 chains) + agg + stats
// ============================================================================
__global__ __launch_bounds__(THREADS, 1)
void k_gcn(const float* __restrict__ x)
{
    extern __shared__ char smem[];
    const uint32_t sbase = smem_u32(smem);
    float* Ysm  = (float*)(smem + Y_B);
    float* Af   = (float*)(smem + AF_B);
    float* be   = (float*)(smem + BE_B);
    float* part = (float*)(smem + PART_B);

    const int tid = threadIdx.x;
    const int wid = tid >> 5;
    const int lid = tid & 31;

    const int bi = blockIdx.x;
    const int n  = bi >> 8;
    const int t0 = (bi & 255) * TPOS;

    // ---- setup: x -> bf16 hi/lo (cin-pairs packed into 4B words), Af/be loads
    const float* xg = x + (size_t)n * (C_ * T_ * V_) + (size_t)t0 * V_;
    for (int i = tid; i < 3200; i += THREADS) {          // 32 cin-pairs x 100 r
        int cp = i / 100, r = i % 100;
        float xa = xg[(size_t)(2 * cp)     * (T_ * V_) + r];
        float xc = xg[(size_t)(2 * cp + 1) * (T_ * V_) + r];
        __nv_bfloat16 ha = __float2bfloat16(xa);
        __nv_bfloat16 hc = __float2bfloat16(xc);
        __nv_bfloat16 la = __float2bfloat16(xa - __bfloat162float(ha));
        __nv_bfloat16 lc = __float2bfloat16(xc - __bfloat162float(hc));
        uint32_t hw = (uint32_t)__bfloat16_as_ushort(ha) | ((uint32_t)__bfloat16_as_ushort(hc) << 16);
        uint32_t lw = (uint32_t)__bfloat16_as_ushort(la) | ((uint32_t)__bfloat16_as_ushort(lc) << 16);
        uint32_t off = SWZ128((uint32_t)(r * 128 + cp * 4));
        *(uint32_t*)(smem + XHI_B + off) = hw;
        *(uint32_t*)(smem + XLO_B + off) = lw;
    }
    for (int i = tid; i < 4 * 32; i += THREADS) {        // zero rows 100-103
        int r = 100 + (i >> 5), cp = i & 31;
        uint32_t off = SWZ128((uint32_t)(r * 128 + cp * 4));
        *(uint32_t*)(smem + XHI_B + off) = 0u;
        *(uint32_t*)(smem + XLO_B + off) = 0u;
    }
    for (int i = tid; i < K_ * V_ * 28; i += THREADS) Af[i] = g_af[i];
    for (int i = tid; i < C_ * V_; i += THREADS)      be[i] = g_beff[i];
    __syncthreads();

    // ---- MMA: 156 items (mt,nt) striped over 16 warps, 3 accumulator chains
    {
        const uint4* wf4 = (const uint4*)g_wfrag;
        for (int it = wid; it < 156; it += 16) {
            const int mt = it % 12;
            const int nt = it / 12;

            uint4 fh[4], fl[4];
            #pragma unroll
            for (int ks = 0; ks < 4; ks++) {
                fh[ks] = wf4[((mt * 4 + ks) * 2 + 0) * 32 + lid];
                fl[ks] = wf4[((mt * 4 + ks) * 2 + 1) * 32 + lid];
            }

            uint32_t bh[8], bl[8];                       // [ks][2]
            #pragma unroll
            for (int k2 = 0; k2 < 2; k2++) {
                uint32_t off = SWZ128((uint32_t)((nt * 8 + (lid & 7)) * 128
                                + k2 * 64 + (lid >> 3) * 16));
                ldsm_x4(sbase + XHI_B + off, bh + k2 * 4);
                ldsm_x4(sbase + XLO_B + off, bl + k2 * 4);
            }

            float hh0=0,hh1=0,hh2=0,hh3=0, lh0=0,lh1=0,lh2=0,lh3=0, hl0=0,hl1=0,hl2=0,hl3=0;
            #pragma unroll
            for (int ks = 0; ks < 4; ks++) {
                uint32_t b0 = bh[ks * 2], b1 = bh[ks * 2 + 1];
                mma_bf16(hh0, hh1, hh2, hh3, fh[ks], b0, b1);
                mma_bf16(lh0, lh1, lh2, lh3, fl[ks], b0, b1);
                mma_bf16(hl0, hl1, hl2, hl3, fh[ks], bl[ks * 2], bl[ks * 2 + 1]);
            }

            const int r0 = mt * 16 + (lid >> 2);
            const int c0 = nt * 8 + (lid & 3) * 2;
            Ysm[r0 * 105 + c0]           = hh0 + lh0 + hl0;
            Ysm[r0 * 105 + c0 + 1]       = hh1 + lh1 + hl1;
            Ysm[(r0 + 8) * 105 + c0]     = hh2 + lh2 + hl2;
            Ysm[(r0 + 8) * 105 + c0 + 1] = hh3 + lh3 + hl3;
        }
    }
    __syncthreads();     // Y ready; X dead -> ags overlays it

    float* ags = (float*)(smem + AGS_B);

    // ---- aggregation: thread owns (c, p, w-half) — identical to R12 ----
    {
        const int c = tid & 63;
        const int p = (tid >> 6) & 3;
        const int h = tid >> 8;
        const int w0 = h * 12;

        unsigned long long acc[6];
        float acc24 = 0.f;
        {
            const float* bec = be + c * 25 + w0;
            #pragma unroll
            for (int j = 0; j < 6; j++) acc[j] = pack2(bec[2 * j], bec[2 * j + 1]);
            if (h) acc24 = be[c * 25 + 24];
        }

        #pragma unroll 1
        for (int k = 0; k < 3; k++) {
            const float* yrow = Ysm + (k * 64 + c) * 105 + p * 25;
            const float* afk  = Af + k * 25 * 28 + w0;
            #pragma unroll 5
            for (int v = 0; v < 25; v++) {
                float yv = yrow[v];
                unsigned long long yp = pack2(yv, yv);
                const ulonglong2* a2 = (const ulonglong2*)(afk + v * 28);
                ulonglong2 aa0 = a2[0];
                acc[0] = fma2(yp, aa0.x, acc[0]);
                acc[1] = fma2(yp, aa0.y, acc[1]);
                unsigned long long aa2 = *(const unsigned long long*)(afk + v * 28 + 4);
                unsigned long long aa3 = *(const unsigned long long*)(afk + v * 28 + 6);
                acc[2] = fma2(yp, aa2, acc[2]);
                acc[3] = fma2(yp, aa3, acc[3]);
                unsigned long long aa4 = *(const unsigned long long*)(afk + v * 28 + 8);
                unsigned long long aa5 = *(const unsigned long long*)(afk + v * 28 + 10);
                acc[4] = fma2(yp, aa4, acc[4]);
                acc[5] = fma2(yp, aa5, acc[5]);
                if (h) acc24 = fmaf(yv, Af[(k * 25 + v) * 28 + 24], acc24);
            }
        }

        float vals[13];
        #pragma unroll
        for (int j = 0; j < 6; j++) unpack2(acc[j], vals[2 * j], vals[2 * j + 1]);
        vals[12] = acc24;
        const int nv = h ? 13 : 12;

        float s1 = 0.f, s2 = 0.f;
        #pragma unroll
        for (int j = 0; j < 13; j++)
            if (j < nv) { float a = vals[j]; s1 += a; s2 += a * a; }

        float* ar = ags + c * 101 + p * 25 + w0;
        #pragma unroll
        for (int j = 0; j < 13; j++)
            if (j < nv) ar[j] = vals[j];

        part[tid] = s1;
        part[THREADS + tid] = s2;
    }
    __syncthreads();

    // ---- coalesced store + deterministic partial reduce ----
    float* ob = g_agg + ((size_t)(n * 64) * T_ + t0) * V_;
    for (int i = tid; i < 6400; i += THREADS) {
        int cc = i / 100, r = i % 100;
        ob[(size_t)cc * (T_ * V_) + r] = ags[cc * 101 + r];
    }
    if (tid < 64) {
        float p1 = 0.f, p2 = 0.f;
        #pragma unroll
        for (int j = 0; j < 8; j++) {
            p1 += part[tid + 64 * j];
            p2 += part[THREADS + tid + 64 * j];
        }
        g_psum[bi * 64 + tid]   = p1;
        g_psumsq[bi * 64 + tid] = p2;
    }
}

// ============================================================================
// Pass 2: reduce partials -> per-channel scale/shift
// ============================================================================
__global__ void k_stats(const float* __restrict__ gamma, const float* __restrict__ beta)
{
    const int ch = blockIdx.x;
    const int tid = threadIdx.x;
    __shared__ float s1s[256], s2s[256];
    float s1 = 0.f, s2 = 0.f;
    for (int j = tid; j < NBLK1; j += 256) {
        s1 += g_psum[j * 64 + ch];
        s2 += g_psumsq[j * 64 + ch];
    }
    s1s[tid] = s1; s2s[tid] = s2;
    __syncthreads();
    for (int st = 128; st > 0; st >>= 1) {
        if (tid < st) { s1s[tid] += s1s[tid + st]; s2s[tid] += s2s[tid + st]; }
        __syncthreads();
    }
    if (tid == 0) {
        const float cnt = (float)N_ * T_ * V_;
        float mu   = s1s[0] / cnt;
        float var  = s2s[0] / cnt - mu * mu;
        float rstd = rsqrtf(var + EPSV);
        float sc   = gamma[ch] * rstd;
        g_scale[ch] = sc;
        g_shift[ch] = beta[ch] - mu * sc;
    }
}

// ============================================================================
// Pass 3: out = relu(agg*scale + shift + x), float4
// ============================================================================
__global__ __launch_bounds__(256)
void k_out(const float* __restrict__ x, float* __restrict__ out)
{
    const int total4 = (N_ * C_ * T_ * V_) / 4;
    int i = blockIdx.x * blockDim.x + threadIdx.x;
    if (i >= total4) return;
    const float4* x4 = (const float4*)x;
    const float4* a4 = (const float4*)g_agg;
    float4* o4 = (float4*)out;

    int c = (i / 6400) & 63;
    float sc = g_scale[c], sh = g_shift[c];
    float4 a = a4[i], xv = x4[i];
    float4 r;
    r.x = fmaxf(fmaf(a.x, sc, sh) + xv.x, 0.f);
    r.y = fmaxf(fmaf(a.y, sc, sh) + xv.y, 0.f);
    r.z = fmaxf(fmaf(a.z, sc, sh) + xv.z, 0.f);
    r.w = fmaxf(fmaf(a.w, sc, sh) + xv.w, 0.f);
    o4[i] = r;
}

// ============================================================================
extern "C" void kernel_launch(void* const* d_in, const int* in_sizes, int n_in,
                              void* d_out, int out_size)
{
    const float* x     = (const float*)d_in[0];
    const float* W     = (const float*)d_in[1];
    const float* b     = (const float*)d_in[2];
    const float* A     = (const float*)d_in[3];
    const float* PA    = (const float*)d_in[4];
    const float* gamma = (const float*)d_in[5];
    const float* beta  = (const float*)d_in[6];
    float* out = (float*)d_out;

    cudaFuncSetAttribute(k_gcn, cudaFuncAttributeMaxDynamicSharedMemorySize, SMEM_TOTAL);

    k_prep<<<1, 1024>>>(W, b, A, PA);
    k_gcn<<<NBLK1, THREADS, SMEM_TOTAL>>>(x);
    k_stats<<<C_, 256>>>(gamma, beta);
    const int total4 = (N_ * C_ * T_ * V_) / 4;
    k_out<<<(total4 + 255) / 256, 256>>>(x, out);
}

// round 15
// speedup vs baseline: 1.6484x; 1.4692x over previous
#include <cuda_runtime.h>
#include <cuda_bf16.h>
#include <cstdint>
#include <cstddef>

// Problem constants
#define N_    32
#define C_    64
#define T_    1024
#define V_    25
#define K_    3
#define O_    192
#define EPSV  1e-5f

#define TPOS  4
#define NBLK1 (N_ * (T_ / TPOS))   // 8192
#define THREADS 256

// ---- smem layout (bytes) for k_gcn ----
#define XHI_B   0        // bf16 [104 pos][64 cin] SW128 rows (13312 B)
#define XLO_B   13312
#define Y_B     26624    // f32 [192][101] = 77568 B (odd stride: conflict-free cols)
#define AF_B    104192   // f32 [3][25][28] = 8400 B
#define PART_B  112592   // f32 [512] = 2048 B
#define SMEM_TOTAL 114640      // 2x fits in 228KB -> 2 CTAs/SM
// overlay after MMA (X dead): ags f32 [64][101] = 25856 B at offset 0
#define AGS_B   0

// ---- device scratch ----
__device__ float    g_agg[(size_t)N_ * C_ * T_ * V_];
__device__ float    g_psum[NBLK1 * C_];
__device__ float    g_psumsq[NBLK1 * C_];
__device__ float    g_scale[C_];
__device__ float    g_shift[C_];
__device__ uint32_t g_wfrag[48 * 2 * 32 * 4];   // [mt*4+ks][hi/lo][lane][4 regs]
__device__ float    g_af[K_ * V_ * 28];         // padded, pads zeroed
__device__ float    g_beff[C_ * V_];            // effective bias

#define SWZ128(o) ((o) ^ (((o) >> 3) & 0x70))

__device__ __forceinline__ uint32_t smem_u32(const void* p) {
    uint32_t a;
    asm("{ .reg .u64 t; cvta.to.shared.u64 t, %1; cvt.u32.u64 %0, t; }" : "=r"(a) : "l"(p));
    return a;
}

// ---- packed fp32x2 ----
__device__ __forceinline__ unsigned long long pack2(float a, float b) {
    unsigned long long r;
    asm("mov.b64 %0, {%1, %2};" : "=l"(r) : "f"(a), "f"(b));
    return r;
}
__device__ __forceinline__ void unpack2(unsigned long long p, float& a, float& b) {
    asm("mov.b64 {%0, %1}, %2;" : "=f"(a), "=f"(b) : "l"(p));
}
__device__ __forceinline__ unsigned long long fma2(unsigned long long a,
                                                   unsigned long long b,
                                                   unsigned long long c) {
    unsigned long long d;
    asm("fma.rn.f32x2 %0, %1, %2, %3;" : "=l"(d) : "l"(a), "l"(b), "l"(c));
    return d;
}

// ---- mma.sync / ldmatrix (plain sm_80+ PTX) ----
__device__ __forceinline__ void ldsm_x4(uint32_t addr, uint32_t* r) {
    asm volatile("ldmatrix.sync.aligned.m8n8.x4.shared.b16 {%0,%1,%2,%3}, [%4];"
        : "=r"(r[0]), "=r"(r[1]), "=r"(r[2]), "=r"(r[3]) : "r"(addr));
}
__device__ __forceinline__ void mma_bf16(float& d0, float& d1, float& d2, float& d3,
                                         uint4 a, uint32_t b0, uint32_t b1) {
    asm volatile("mma.sync.aligned.m16n8k16.row.col.f32.bf16.bf16.f32 "
        "{%0,%1,%2,%3}, {%4,%5,%6,%7}, {%8,%9}, {%0,%1,%2,%3};"
        : "+f"(d0), "+f"(d1), "+f"(d2), "+f"(d3)
        : "r"(a.x), "r"(a.y), "r"(a.z), "r"(a.w), "r"(b0), "r"(b1));
}

// ============================================================================
// k_prep: once per launch — W fragments (bf16 hi/lo, mma A-frag order),
//         Af = A+PA (padded), effective bias.
// ============================================================================
__global__ __launch_bounds__(1024)
void k_prep(const float* __restrict__ W, const float* __restrict__ b,
            const float* __restrict__ A, const float* __restrict__ PA)
{
    __shared__ float saf[K_ * V_ * 28];
    __shared__ float scs[K_ * V_];
    const int tid = threadIdx.x;

    for (int idx = tid; idx < 6144; idx += 1024) {
        int j    = idx & 3;
        int lane = (idx >> 2) & 31;
        int mtks = idx >> 7;
        int mt = mtks >> 2, ks = mtks & 3;
        int g = lane >> 2, tg = lane & 3;
        int row = mt * 16 + g + ((j & 1) << 3);
        int col = ks * 16 + tg * 2 + ((j >> 1) << 3);
        float w0 = W[row * 64 + col], w1 = W[row * 64 + col + 1];
        __nv_bfloat16 h0 = __float2bfloat16(w0);
        __nv_bfloat16 h1 = __float2bfloat16(w1);
        __nv_bfloat16 l0 = __float2bfloat16(w0 - __bfloat162float(h0));
        __nv_bfloat16 l1 = __float2bfloat16(w1 - __bfloat162float(h1));
        uint32_t hw = (uint32_t)__bfloat16_as_ushort(h0) | ((uint32_t)__bfloat16_as_ushort(h1) << 16);
        uint32_t lw = (uint32_t)__bfloat16_as_ushort(l0) | ((uint32_t)__bfloat16_as_ushort(l1) << 16);
        g_wfrag[((mtks * 2 + 0) * 32 + lane) * 4 + j] = hw;
        g_wfrag[((mtks * 2 + 1) * 32 + lane) * 4 + j] = lw;
    }
    for (int i = tid; i < K_ * V_ * 28; i += 1024) {
        int kv = i / 28, w = i % 28;
        float v = (w < 25) ? (A[kv * 25 + w] + PA[kv * 25 + w]) : 0.f;
        saf[i] = v;
        g_af[i] = v;
    }
    __syncthreads();
    if (tid < 75) {
        int k = tid / 25, w = tid % 25;
        float s = 0.f;
        #pragma unroll
        for (int v = 0; v < 25; v++) s += saf[(k * 25 + v) * 28 + w];
        scs[tid] = s;
    }
    __syncthreads();
    for (int i = tid; i < C_ * V_; i += 1024) {
        int c = i / 25, w = i % 25;
        float s = 0.f;
        #pragma unroll
        for (int k = 0; k < 3; k++) s += b[k * 64 + c] * scs[k * 25 + w];
        g_beff[i] = s;
    }
}

// ============================================================================
// Pass 1: HMMA conv (warp-owns-mt, A-frags resident) + agg + stats; 2 CTAs/SM
// ============================================================================
__global__ __launch_bounds__(THREADS, 2)
void k_gcn(const float* __restrict__ x)
{
    extern __shared__ char smem[];
    const uint32_t sbase = smem_u32(smem);
    float* Ysm  = (float*)(smem + Y_B);
    float* Af   = (float*)(smem + AF_B);
    float* part = (float*)(smem + PART_B);

    const int tid = threadIdx.x;
    const int wid = tid >> 5;
    const int lid = tid & 31;

    const int bi = blockIdx.x;
    const int n  = bi >> 8;
    const int t0 = (bi & 255) * TPOS;

    // ---- setup: x -> bf16 hi/lo (cin-pairs packed), Af copy ----
    const float* xg = x + (size_t)n * (C_ * T_ * V_) + (size_t)t0 * V_;
    for (int i = tid; i < 3200; i += THREADS) {          // 32 cin-pairs x 100 r
        int cp = i / 100, r = i % 100;
        float xa = xg[(size_t)(2 * cp)     * (T_ * V_) + r];
        float xc = xg[(size_t)(2 * cp + 1) * (T_ * V_) + r];
        __nv_bfloat16 ha = __float2bfloat16(xa);
        __nv_bfloat16 hc = __float2bfloat16(xc);
        __nv_bfloat16 la = __float2bfloat16(xa - __bfloat162float(ha));
        __nv_bfloat16 lc = __float2bfloat16(xc - __bfloat162float(hc));
        uint32_t hw = (uint32_t)__bfloat16_as_ushort(ha) | ((uint32_t)__bfloat16_as_ushort(hc) << 16);
        uint32_t lw = (uint32_t)__bfloat16_as_ushort(la) | ((uint32_t)__bfloat16_as_ushort(lc) << 16);
        uint32_t off = SWZ128((uint32_t)(r * 128 + cp * 4));
        *(uint32_t*)(smem + XHI_B + off) = hw;
        *(uint32_t*)(smem + XLO_B + off) = lw;
    }
    for (int i = tid; i < 4 * 32; i += THREADS) {        // zero rows 100-103
        int r = 100 + (i >> 5), cp = i & 31;
        uint32_t off = SWZ128((uint32_t)(r * 128 + cp * 4));
        *(uint32_t*)(smem + XHI_B + off) = 0u;
        *(uint32_t*)(smem + XLO_B + off) = 0u;
    }
    for (int i = tid; i < K_ * V_ * 28; i += THREADS) Af[i] = g_af[i];
    __syncthreads();

    // ---- MMA: 24 items (mt, nt-half) over 8 warps; A-frags live in regs ----
    {
        const uint4* wf4 = (const uint4*)g_wfrag;
        for (int it = wid; it < 24; it += 8) {
            const int mt   = it >> 1;
            const int half = it & 1;
            const int nt0  = half * 7;
            const int nt1  = half ? 13 : 7;

            uint4 fh[4], fl[4];
            #pragma unroll
            for (int ks = 0; ks < 4; ks++) {
                fh[ks] = wf4[((mt * 4 + ks) * 2 + 0) * 32 + lid];
                fl[ks] = wf4[((mt * 4 + ks) * 2 + 1) * 32 + lid];
            }

            for (int nt = nt0; nt < nt1; nt++) {
                uint32_t bh[8], bl[8];
                #pragma unroll
                for (int k2 = 0; k2 < 2; k2++) {
                    uint32_t off = SWZ128((uint32_t)((nt * 8 + (lid & 7)) * 128
                                    + k2 * 64 + (lid >> 3) * 16));
                    ldsm_x4(sbase + XHI_B + off, bh + k2 * 4);
                    ldsm_x4(sbase + XLO_B + off, bl + k2 * 4);
                }

                float hh0=0,hh1=0,hh2=0,hh3=0, lh0=0,lh1=0,lh2=0,lh3=0, hl0=0,hl1=0,hl2=0,hl3=0;
                #pragma unroll
                for (int ks = 0; ks < 4; ks++) {
                    uint32_t b0 = bh[ks * 2], b1 = bh[ks * 2 + 1];
                    mma_bf16(hh0, hh1, hh2, hh3, fh[ks], b0, b1);
                    mma_bf16(lh0, lh1, lh2, lh3, fl[ks], b0, b1);
                    mma_bf16(hl0, hl1, hl2, hl3, fh[ks], bl[ks * 2], bl[ks * 2 + 1]);
                }

                const int r0 = mt * 16 + (lid >> 2);
                const int c0 = nt * 8 + (lid & 3) * 2;
                if (c0 < 100) {       // cols 100-103 don't exist (pairs never straddle 100)
                    Ysm[r0 * 101 + c0]           = hh0 + lh0 + hl0;
                    Ysm[r0 * 101 + c0 + 1]       = hh1 + lh1 + hl1;
                    Ysm[(r0 + 8) * 101 + c0]     = hh2 + lh2 + hl2;
                    Ysm[(r0 + 8) * 101 + c0 + 1] = hh3 + lh3 + hl3;
                }
            }
        }
    }
    __syncthreads();     // Y ready; X dead -> ags overlays it

    float* ags = (float*)(smem + AGS_B);

    // ---- aggregation: thread owns (c, p), full w range ----
    {
        const int c = tid & 63;
        const int p = tid >> 6;

        unsigned long long acc[12];
        float acc24;
        {
            const float* bec = g_beff + c * 25;
            #pragma unroll
            for (int j = 0; j < 12; j++) acc[j] = pack2(__ldg(bec + 2 * j), __ldg(bec + 2 * j + 1));
            acc24 = __ldg(bec + 24);
        }

        #pragma unroll 1
        for (int k = 0; k < 3; k++) {
            const float* yrow = Ysm + (k * 64 + c) * 101 + p * 25;   // stride 101: conflict-free
            #pragma unroll 5
            for (int v = 0; v < 25; v++) {
                float yv = yrow[v];
                unsigned long long yp = pack2(yv, yv);
                const float* ar = Af + (k * 25 + v) * 28;            // 16B-aligned row
                const ulonglong2* a2 = (const ulonglong2*)ar;
                #pragma unroll
                for (int q = 0; q < 6; q++) {
                    ulonglong2 aa = a2[q];
                    acc[2 * q + 0] = fma2(yp, aa.x, acc[2 * q + 0]);
                    acc[2 * q + 1] = fma2(yp, aa.y, acc[2 * q + 1]);
                }
                acc24 = fmaf(yv, ar[24], acc24);
            }
        }

        float aggv[25];
        #pragma unroll
        for (int j = 0; j < 12; j++) unpack2(acc[j], aggv[2 * j], aggv[2 * j + 1]);
        aggv[24] = acc24;

        float s1 = 0.f, s2 = 0.f;
        #pragma unroll
        for (int w = 0; w < 25; w++) { float a = aggv[w]; s1 += a; s2 += a * a; }

        float* ar2 = ags + c * 101 + p * 25;
        #pragma unroll
        for (int w = 0; w < 25; w++) ar2[w] = aggv[w];

        part[tid] = s1;
        part[256 + tid] = s2;
    }
    __syncthreads();

    // ---- coalesced store + deterministic partial reduce ----
    float* ob = g_agg + ((size_t)(n * 64) * T_ + t0) * V_;
    for (int i = tid; i < 6400; i += THREADS) {
        int cc = i / 100, r = i % 100;
        ob[(size_t)cc * (T_ * V_) + r] = ags[cc * 101 + r];
    }
    if (tid < 64) {
        float p1 = part[tid] + part[64 + tid] + part[128 + tid] + part[192 + tid];
        float p2 = part[256 + tid] + part[320 + tid] + part[384 + tid] + part[448 + tid];
        g_psum[bi * 64 + tid]   = p1;
        g_psumsq[bi * 64 + tid] = p2;
    }
}

// ============================================================================
// Pass 2: reduce partials -> per-channel scale/shift
// ============================================================================
__global__ void k_stats(const float* __restrict__ gamma, const float* __restrict__ beta)
{
    const int ch = blockIdx.x;
    const int tid = threadIdx.x;
    __shared__ float s1s[256], s2s[256];
    float s1 = 0.f, s2 = 0.f;
    for (int j = tid; j < NBLK1; j += 256) {
        s1 += g_psum[j * 64 + ch];
        s2 += g_psumsq[j * 64 + ch];
    }
    s1s[tid] = s1; s2s[tid] = s2;
    __syncthreads();
    for (int st = 128; st > 0; st >>= 1) {
        if (tid < st) { s1s[tid] += s1s[tid + st]; s2s[tid] += s2s[tid + st]; }
        __syncthreads();
    }
    if (tid == 0) {
        const float cnt = (float)N_ * T_ * V_;
        float mu   = s1s[0] / cnt;
        float var  = s2s[0] / cnt - mu * mu;
        float rstd = rsqrtf(var + EPSV);
        float sc   = gamma[ch] * rstd;
        g_scale[ch] = sc;
        g_shift[ch] = beta[ch] - mu * sc;
    }
}

// ============================================================================
// Pass 3: out = relu(agg*scale + shift + x), float4
// ============================================================================
__global__ __launch_bounds__(256)
void k_out(const float* __restrict__ x, float* __restrict__ out)
{
    const int total4 = (N_ * C_ * T_ * V_) / 4;
    int i = blockIdx.x * blockDim.x + threadIdx.x;
    if (i >= total4) return;
    const float4* x4 = (const float4*)x;
    const float4* a4 = (const float4*)g_agg;
    float4* o4 = (float4*)out;

    int c = (i / 6400) & 63;
    float sc = g_scale[c], sh = g_shift[c];
    float4 a = a4[i], xv = x4[i];
    float4 r;
    r.x = fmaxf(fmaf(a.x, sc, sh) + xv.x, 0.f);
    r.y = fmaxf(fmaf(a.y, sc, sh) + xv.y, 0.f);
    r.z = fmaxf(fmaf(a.z, sc, sh) + xv.z, 0.f);
    r.w = fmaxf(fmaf(a.w, sc, sh) + xv.w, 0.f);
    o4[i] = r;
}

// ============================================================================
extern "C" void kernel_launch(void* const* d_in, const int* in_sizes, int n_in,
                              void* d_out, int out_size)
{
    const float* x     = (const float*)d_in[0];
    const float* W     = (const float*)d_in[1];
    const float* b     = (const float*)d_in[2];
    const float* A     = (const float*)d_in[3];
    const float* PA    = (const float*)d_in[4];
    const float* gamma = (const float*)d_in[5];
    const float* beta  = (const float*)d_in[6];
    float* out = (float*)d_out;

    cudaFuncSetAttribute(k_gcn, cudaFuncAttributeMaxDynamicSharedMemorySize, SMEM_TOTAL);

    k_prep<<<1, 1024>>>(W, b, A, PA);
    k_gcn<<<NBLK1, THREADS, SMEM_TOTAL>>>(x);
    k_stats<<<C_, 256>>>(gamma, beta);
    const int total4 = (N_ * C_ * T_ * V_) / 4;
    k_out<<<(total4 + 255) / 256, 256>>>(x, out);
}